// round 10
// baseline (speedup 1.0000x reference)
#include <cuda_runtime.h>

#define BATCH   4
#define NPTS    8192
#define KNN     8
#define TILE    1024
#define QBLK    64       // queries per block
#define THREADS 128      // 2 threads per query (candidate split)
#define NTILES  (NPTS / TILE)          // 8
#define BLKS_PER_TILE (TILE / QBLK)    // 16

typedef unsigned long long u64;

__device__ float4 g_pred4[BATCH * NPTS];
__device__ float4 g_targ4[BATCH * NPTS];
__device__ float4 g_pred4s[BATCH * NPTS];   // Morton-sorted queries
__device__ float4 g_targ4s[BATCH * NPTS];
__device__ unsigned g_key[2][BATCH * NPTS]; // (morton18 << 13) | idx13
// Morton-sorted candidate SoA: set 0 = pred-sorted, set 1 = targ-sorted
__device__ float g_sx[2 * BATCH * NPTS];
__device__ float g_sy[2 * BATCH * NPTS];
__device__ float g_sz[2 * BATCH * NPTS];
__device__ float g_sw[2 * BATCH * NPTS];

__device__ __forceinline__ u64 pack2(float lo, float hi) {
    u64 r;
    asm("mov.b64 %0, {%1, %2};" : "=l"(r) : "f"(lo), "f"(hi));
    return r;
}
__device__ __forceinline__ float lo32(u64 v) { return __uint_as_float((unsigned)v); }
__device__ __forceinline__ float hi32(u64 v) { return __uint_as_float((unsigned)(v >> 32)); }
__device__ __forceinline__ u64 ffma2(u64 a, u64 b, u64 c) {
    u64 d;
    asm("fma.rn.f32x2 %0, %1, %2, %3;" : "=l"(d) : "l"(a), "l"(b), "l"(c));
    return d;
}

__device__ __forceinline__ unsigned morton18(float x, float y, float z) {
    int ax = (int)((x + 4.0f) * 8.0f); ax = ax < 0 ? 0 : (ax > 63 ? 63 : ax);
    int ay = (int)((y + 4.0f) * 8.0f); ay = ay < 0 ? 0 : (ay > 63 ? 63 : ay);
    int az = (int)((z + 4.0f) * 8.0f); az = az < 0 ? 0 : (az > 63 ? 63 : az);
    unsigned m = 0;
#pragma unroll
    for (int bit = 0; bit < 6; ++bit) {
        m |= ((unsigned)((ax >> bit) & 1)) << (3 * bit + 2);
        m |= ((unsigned)((ay >> bit) & 1)) << (3 * bit + 1);
        m |= ((unsigned)((az >> bit) & 1)) << (3 * bit + 0);
    }
    return m;
}

__global__ void prep_kernel(const float* __restrict__ src,
                            const float* __restrict__ tgt,
                            const float* __restrict__ flow) {
    int i = blockIdx.x * blockDim.x + threadIdx.x;
    if (i >= BATCH * NPTS) return;
    int li = i & (NPTS - 1);

    float px = src[3 * i + 0] + flow[3 * i + 0];
    float py = src[3 * i + 1] + flow[3 * i + 1];
    float pz = src[3 * i + 2] + flow[3 * i + 2];
    float pw = px * px + py * py + pz * pz;
    g_pred4[i] = make_float4(px, py, pz, pw);
    g_key[0][i] = (morton18(px, py, pz) << 13) | (unsigned)li;

    float tx = tgt[3 * i + 0], ty = tgt[3 * i + 1], tz = tgt[3 * i + 2];
    float tw = tx * tx + ty * ty + tz * tz;
    g_targ4[i] = make_float4(tx, ty, tz, tw);
    g_key[1][i] = (morton18(tx, ty, tz) << 13) | (unsigned)li;
}

// Bitonic sort of 8192 packed keys in smem, then permute queries AND
// candidate SoA arrays. grid = 8 blocks: blockIdx.x = set * BATCH + batch
__global__ void __launch_bounds__(1024)
sort_kernel() {
    __shared__ unsigned sk[NPTS];
    const int set = blockIdx.x >> 2;       // 0 = pred, 1 = targ
    const int b   = blockIdx.x & 3;
    const int tid = threadIdx.x;

    for (int i = tid; i < NPTS; i += 1024)
        sk[i] = g_key[set][b * NPTS + i];

    for (int k = 2; k <= NPTS; k <<= 1) {
        for (int j = k >> 1; j > 0; j >>= 1) {
            __syncthreads();
            for (int i = tid; i < NPTS; i += 1024) {
                int ixj = i ^ j;
                if (ixj > i) {
                    unsigned a = sk[i], c = sk[ixj];
                    bool up = ((i & k) == 0);
                    if ((a > c) == up) { sk[i] = c; sk[ixj] = a; }
                }
            }
        }
    }
    __syncthreads();

    const float4* src4 = (set == 0 ? g_pred4 : g_targ4) + b * NPTS;
    float4* dst4 = (set == 0 ? g_pred4s : g_targ4s) + b * NPTS;
    const int so = set * BATCH * NPTS + b * NPTS;
    for (int i = tid; i < NPTS; i += 1024) {
        float4 p = src4[sk[i] & (NPTS - 1)];
        dst4[i] = p;
        g_sx[so + i] = p.x;
        g_sy[so + i] = p.y;
        g_sz[so + i] = p.z;
        g_sw[so + i] = p.w;
    }
}

// Branchless sorted-descending insert (caller guarantees val < h[0])
#define INSERT8(h, val)                          \
    do {                                         \
        float _v = (val);                        \
        _Pragma("unroll")                        \
        for (int _i = 0; _i < KNN - 1; ++_i) {   \
            float _nx = h[_i + 1];               \
            h[_i] = fmaxf(_v, _nx);              \
            _v = fminf(_v, _nx);                 \
        }                                        \
        h[KNN - 1] = _v;                         \
    } while (0)

#define TRYINS(h, val) do { if ((val) < h[0]) INSERT8(h, (val)); } while (0)

__global__ void __launch_bounds__(THREADS, 8)
chamfer_kernel(float* __restrict__ out) {
    // x @ 0, y @ TILE, z @ 2*TILE, w @ 3*TILE
    __shared__ __align__(16) float sm[4 * TILE];
    __shared__ float m8[QBLK][KNN];
    __shared__ float red[QBLK];

    const int b   = blockIdx.y;
    const int dir = blockIdx.z;
    // dir 0: queries = sorted pred, candidates = sorted targ (set 1)
    // dir 1: queries = sorted targ, candidates = sorted pred (set 0)
    const float4* q4 = (dir == 0 ? g_pred4s : g_targ4s) + b * NPTS;
    const int coff = (dir == 0 ? 1 : 0) * BATCH * NPTS + b * NPTS;

    const int qt   = threadIdx.x & (QBLK - 1);
    const int half = threadIdx.x >> 6;       // warp-uniform
    const int qi   = blockIdx.x * QBLK + qt;
    const float4 q = q4[qi];
    const u64 ax2 = pack2(-2.0f * q.x, -2.0f * q.x);
    const u64 ay2 = pack2(-2.0f * q.y, -2.0f * q.y);
    const u64 az2 = pack2(-2.0f * q.z, -2.0f * q.z);

    float h[KNN];
#pragma unroll
    for (int i = 0; i < KNN; ++i) h[i] = 1.0e30f;

    // Home tile first: both sets Morton-sorted & same distribution, so the
    // candidates rank-aligned with this block's queries are the near ones.
    const int thome = blockIdx.x / BLKS_PER_TILE;

    for (int ti = 0; ti < NTILES; ++ti) {
        const int t0 = ((thome + ti) & (NTILES - 1)) * TILE;
        __syncthreads();
#pragma unroll
        for (int l = threadIdx.x; l < TILE / 4; l += THREADS) {
            ((float4*)sm)[l]              = ((const float4*)(g_sx + coff + t0))[l];
            ((float4*)(sm + TILE))[l]     = ((const float4*)(g_sy + coff + t0))[l];
            ((float4*)(sm + 2 * TILE))[l] = ((const float4*)(g_sz + coff + t0))[l];
            ((float4*)(sm + 3 * TILE))[l] = ((const float4*)(g_sw + coff + t0))[l];
        }
        __syncthreads();

        // Each thread: interleaved 4-candidate groups, stride 8
        const float* base = sm + 4 * half;
#pragma unroll 4
        for (int j = 0; j < TILE; j += 8) {
            const ulonglong2 X = *(const ulonglong2*)(base + j);
            const ulonglong2 Y = *(const ulonglong2*)(base + j + TILE);
            const ulonglong2 Z = *(const ulonglong2*)(base + j + 2 * TILE);
            const ulonglong2 W = *(const ulonglong2*)(base + j + 3 * TILE);

            // t = |c|^2 - 2 q.c  (ranking key; |q|^2 re-added at the end)
            u64 t01 = ffma2(ax2, X.x, ffma2(ay2, Y.x, ffma2(az2, Z.x, W.x)));
            u64 t23 = ffma2(ax2, X.y, ffma2(ay2, Y.y, ffma2(az2, Z.y, W.y)));

            float f0 = lo32(t01), f1 = hi32(t01);
            float f2 = lo32(t23), f3 = hi32(t23);

            float m = fminf(fminf(f0, f1), fminf(f2, f3));
            if (m < h[0]) {
                TRYINS(h, f0); TRYINS(h, f1);
                TRYINS(h, f2); TRYINS(h, f3);
            }
        }
    }

    // Merge the two halves' top-8 lists
    if (half) {
#pragma unroll
        for (int i = 0; i < KNN; ++i) m8[qt][i] = h[i];
    }
    __syncthreads();
    if (!half) {
#pragma unroll
        for (int i = 0; i < KNN; ++i)
            TRYINS(h, m8[qt][i]);
        float s = 0.0f;
#pragma unroll
        for (int i = 0; i < KNN; ++i)
            s += sqrtf(fmaxf(q.w + h[i], 0.0f));
        red[qt] = s;
    }
    __syncthreads();
#pragma unroll
    for (int off = QBLK / 2; off > 0; off >>= 1) {
        if (threadIdx.x < off) red[threadIdx.x] += red[threadIdx.x + off];
        __syncthreads();
    }
    if (threadIdx.x == 0)
        atomicAdd(out, red[0] * (1.0f / (KNN * BATCH * NPTS)));
}

extern "C" void kernel_launch(void* const* d_in, const int* in_sizes, int n_in,
                              void* d_out, int out_size) {
    const float* src  = (const float*)d_in[0];
    const float* tgt  = (const float*)d_in[1];
    const float* flow = (const float*)d_in[2];
    float* out = (float*)d_out;

    cudaMemsetAsync(out, 0, sizeof(float), 0);

    int npts = BATCH * NPTS;
    prep_kernel<<<(npts + 255) / 256, 256>>>(src, tgt, flow);
    sort_kernel<<<8, 1024>>>();

    dim3 grid(NPTS / QBLK, BATCH, 2);
    chamfer_kernel<<<grid, THREADS>>>(out);
}

// round 11
// speedup vs baseline: 1.0087x; 1.0087x over previous
#include <cuda_runtime.h>

#define BATCH   4
#define NPTS    8192
#define KNN     8
#define TILE    1024
#define NTILES  (NPTS / TILE)   // 8
#define QBLK    64              // queries per block
#define THREADS 128             // 2 threads per query

typedef unsigned long long u64;

__device__ float4 g_pred4[BATCH * NPTS];
__device__ float4 g_targ4[BATCH * NPTS];
__device__ float4 g_pred4s[BATCH * NPTS];   // Morton-sorted queries
__device__ float4 g_targ4s[BATCH * NPTS];
__device__ unsigned g_key[2][BATCH * NPTS]; // (morton18 << 13) | idx13
// Morton-sorted candidate SoA: index = (set*BATCH + b)*NPTS + i
__device__ float g_sx[2 * BATCH * NPTS];
__device__ float g_sy[2 * BATCH * NPTS];
__device__ float g_sz[2 * BATCH * NPTS];
__device__ float g_sw[2 * BATCH * NPTS];
// Tile AABBs: [(set*BATCH+b)*NTILES + t] * 6 : xlo,ylo,zlo,xhi,yhi,zhi
__device__ float g_tbox[2 * BATCH * NTILES * 6];

__device__ __forceinline__ u64 pack2(float lo, float hi) {
    u64 r;
    asm("mov.b64 %0, {%1, %2};" : "=l"(r) : "f"(lo), "f"(hi));
    return r;
}
__device__ __forceinline__ float lo32(u64 v) { return __uint_as_float((unsigned)v); }
__device__ __forceinline__ float hi32(u64 v) { return __uint_as_float((unsigned)(v >> 32)); }
__device__ __forceinline__ u64 ffma2(u64 a, u64 b, u64 c) {
    u64 d;
    asm("fma.rn.f32x2 %0, %1, %2, %3;" : "=l"(d) : "l"(a), "l"(b), "l"(c));
    return d;
}

__device__ __forceinline__ unsigned morton18(float x, float y, float z) {
    int ax = (int)((x + 4.0f) * 8.0f); ax = ax < 0 ? 0 : (ax > 63 ? 63 : ax);
    int ay = (int)((y + 4.0f) * 8.0f); ay = ay < 0 ? 0 : (ay > 63 ? 63 : ay);
    int az = (int)((z + 4.0f) * 8.0f); az = az < 0 ? 0 : (az > 63 ? 63 : az);
    unsigned m = 0;
#pragma unroll
    for (int bit = 0; bit < 6; ++bit) {
        m |= ((unsigned)((ax >> bit) & 1)) << (3 * bit + 2);
        m |= ((unsigned)((ay >> bit) & 1)) << (3 * bit + 1);
        m |= ((unsigned)((az >> bit) & 1)) << (3 * bit + 0);
    }
    return m;
}

__global__ void prep_kernel(const float* __restrict__ src,
                            const float* __restrict__ tgt,
                            const float* __restrict__ flow) {
    int i = blockIdx.x * blockDim.x + threadIdx.x;
    if (i >= BATCH * NPTS) return;
    int li = i & (NPTS - 1);

    float px = src[3 * i + 0] + flow[3 * i + 0];
    float py = src[3 * i + 1] + flow[3 * i + 1];
    float pz = src[3 * i + 2] + flow[3 * i + 2];
    g_pred4[i] = make_float4(px, py, pz, px * px + py * py + pz * pz);
    g_key[0][i] = (morton18(px, py, pz) << 13) | (unsigned)li;

    float tx = tgt[3 * i + 0], ty = tgt[3 * i + 1], tz = tgt[3 * i + 2];
    g_targ4[i] = make_float4(tx, ty, tz, tx * tx + ty * ty + tz * tz);
    g_key[1][i] = (morton18(tx, ty, tz) << 13) | (unsigned)li;
}

// Bitonic sort of 8192 keys in smem; permute queries AND candidate SoA.
__global__ void __launch_bounds__(1024)
sort_kernel() {
    __shared__ unsigned sk[NPTS];
    const int set = blockIdx.x >> 2;
    const int b   = blockIdx.x & 3;
    const int tid = threadIdx.x;

    for (int i = tid; i < NPTS; i += 1024)
        sk[i] = g_key[set][b * NPTS + i];

    for (int k = 2; k <= NPTS; k <<= 1) {
        for (int j = k >> 1; j > 0; j >>= 1) {
            __syncthreads();
            for (int i = tid; i < NPTS; i += 1024) {
                int ixj = i ^ j;
                if (ixj > i) {
                    unsigned a = sk[i], c = sk[ixj];
                    bool up = ((i & k) == 0);
                    if ((a > c) == up) { sk[i] = c; sk[ixj] = a; }
                }
            }
        }
    }
    __syncthreads();

    const float4* src4 = (set == 0 ? g_pred4 : g_targ4) + b * NPTS;
    float4* dst4 = (set == 0 ? g_pred4s : g_targ4s) + b * NPTS;
    const int so = (set * BATCH + b) * NPTS;
    for (int i = tid; i < NPTS; i += 1024) {
        float4 p = src4[sk[i] & (NPTS - 1)];
        dst4[i] = p;
        g_sx[so + i] = p.x;
        g_sy[so + i] = p.y;
        g_sz[so + i] = p.z;
        g_sw[so + i] = p.w;
    }
}

// Per-tile AABB. blockIdx.x = (set*BATCH+b)*NTILES + t, 256 threads.
__global__ void __launch_bounds__(256)
tbox_kernel() {
    __shared__ float rlo[3][256], rhi[3][256];
    const int id  = blockIdx.x;
    const int t   = id % NTILES;
    const int sb  = id / NTILES;
    const int bse = sb * NPTS + t * TILE;
    const int tid = threadIdx.x;

    float lx = 1e30f, ly = 1e30f, lz = 1e30f;
    float hx = -1e30f, hy = -1e30f, hz = -1e30f;
    for (int i = tid; i < TILE; i += 256) {
        float x = g_sx[bse + i], y = g_sy[bse + i], z = g_sz[bse + i];
        lx = fminf(lx, x); ly = fminf(ly, y); lz = fminf(lz, z);
        hx = fmaxf(hx, x); hy = fmaxf(hy, y); hz = fmaxf(hz, z);
    }
    rlo[0][tid] = lx; rlo[1][tid] = ly; rlo[2][tid] = lz;
    rhi[0][tid] = hx; rhi[1][tid] = hy; rhi[2][tid] = hz;
    __syncthreads();
    for (int off = 128; off > 0; off >>= 1) {
        if (tid < off) {
#pragma unroll
            for (int d = 0; d < 3; ++d) {
                rlo[d][tid] = fminf(rlo[d][tid], rlo[d][tid + off]);
                rhi[d][tid] = fmaxf(rhi[d][tid], rhi[d][tid + off]);
            }
        }
        __syncthreads();
    }
    if (tid == 0) {
        g_tbox[id * 6 + 0] = rlo[0][0];
        g_tbox[id * 6 + 1] = rlo[1][0];
        g_tbox[id * 6 + 2] = rlo[2][0];
        g_tbox[id * 6 + 3] = rhi[0][0];
        g_tbox[id * 6 + 4] = rhi[1][0];
        g_tbox[id * 6 + 5] = rhi[2][0];
    }
}

// Branchless sorted-descending insert (caller guarantees val < h[0])
#define INSERT8(h, val)                          \
    do {                                         \
        float _v = (val);                        \
        _Pragma("unroll")                        \
        for (int _i = 0; _i < KNN - 1; ++_i) {   \
            float _nx = h[_i + 1];               \
            h[_i] = fmaxf(_v, _nx);              \
            _v = fminf(_v, _nx);                 \
        }                                        \
        h[KNN - 1] = _v;                         \
    } while (0)

#define TRYINS(h, val) do { if ((val) < h[0]) INSERT8(h, (val)); } while (0)

__global__ void __launch_bounds__(THREADS, 8)
chamfer_kernel(float* __restrict__ out) {
    __shared__ __align__(16) float sm[4 * TILE];
    __shared__ float m8[QBLK][KNN];
    __shared__ float red[THREADS];
    __shared__ float qpart[4][6];
    __shared__ float rpart[4];
    __shared__ float mind2s[NTILES];
    __shared__ int   order_s[NTILES];
    __shared__ float R2s;

    const int b   = blockIdx.y;
    const int dir = blockIdx.z;
    const float4* q4 = (dir == 0 ? g_pred4s : g_targ4s) + b * NPTS;
    const int sb   = (dir == 0 ? 1 : 0) * BATCH + b;   // candidate set-batch
    const int coff = sb * NPTS;

    const int qt   = threadIdx.x & (QBLK - 1);
    const int half = threadIdx.x >> 6;       // warp-uniform
    const int warp = threadIdx.x >> 5;
    const int lane = threadIdx.x & 31;
    const int qi   = blockIdx.x * QBLK + qt;
    const float4 q = q4[qi];
    const u64 ax2 = pack2(-2.0f * q.x, -2.0f * q.x);
    const u64 ay2 = pack2(-2.0f * q.y, -2.0f * q.y);
    const u64 az2 = pack2(-2.0f * q.z, -2.0f * q.z);

    // ---- query-block AABB (all 128 threads; both halves hold same queries)
    {
        float lx = q.x, ly = q.y, lz = q.z;
        float hx = q.x, hy = q.y, hz = q.z;
#pragma unroll
        for (int off = 16; off > 0; off >>= 1) {
            lx = fminf(lx, __shfl_xor_sync(0xFFFFFFFFu, lx, off));
            ly = fminf(ly, __shfl_xor_sync(0xFFFFFFFFu, ly, off));
            lz = fminf(lz, __shfl_xor_sync(0xFFFFFFFFu, lz, off));
            hx = fmaxf(hx, __shfl_xor_sync(0xFFFFFFFFu, hx, off));
            hy = fmaxf(hy, __shfl_xor_sync(0xFFFFFFFFu, hy, off));
            hz = fmaxf(hz, __shfl_xor_sync(0xFFFFFFFFu, hz, off));
        }
        if (lane == 0) {
            qpart[warp][0] = lx; qpart[warp][1] = ly; qpart[warp][2] = lz;
            qpart[warp][3] = hx; qpart[warp][4] = hy; qpart[warp][5] = hz;
        }
    }
    __syncthreads();

    // ---- thread 0: combine AABB, compute per-tile mindist^2, sort ascending
    if (threadIdx.x == 0) {
        float qb[6];
#pragma unroll
        for (int d = 0; d < 3; ++d) {
            qb[d]     = fminf(fminf(qpart[0][d], qpart[1][d]),
                              fminf(qpart[2][d], qpart[3][d]));
            qb[d + 3] = fmaxf(fmaxf(qpart[0][d + 3], qpart[1][d + 3]),
                              fmaxf(qpart[2][d + 3], qpart[3][d + 3]));
        }
        float md[NTILES];
        int   od[NTILES];
#pragma unroll
        for (int t = 0; t < NTILES; ++t) {
            const float* tb = g_tbox + (sb * NTILES + t) * 6;
            float s = 0.0f;
#pragma unroll
            for (int d = 0; d < 3; ++d) {
                float g = fmaxf(fmaxf(tb[d] - qb[d + 3], qb[d] - tb[d + 3]), 0.0f);
                s += g * g;
            }
            md[t] = s;
            od[t] = t;
        }
        // insertion sort ascending by md
#pragma unroll
        for (int i = 1; i < NTILES; ++i) {
            float mv = md[i]; int ov = od[i];
            int j = i;
            while (j > 0 && md[j - 1] > mv) { md[j] = md[j - 1]; od[j] = od[j - 1]; --j; }
            md[j] = mv; od[j] = ov;
        }
#pragma unroll
        for (int t = 0; t < NTILES; ++t) { mind2s[t] = md[t]; order_s[t] = od[t]; }
        R2s = 1e30f;
    }

    float h[KNN];
#pragma unroll
    for (int i = 0; i < KNN; ++i) h[i] = 1.0e30f;

    __syncthreads();

    for (int k = 0; k < NTILES; ++k) {
        if (k > 0 && mind2s[k] > R2s) break;   // block-uniform, safe
        const int t0 = order_s[k] * TILE;
        __syncthreads();
#pragma unroll
        for (int l = threadIdx.x; l < TILE / 4; l += THREADS) {
            ((float4*)sm)[l]              = ((const float4*)(g_sx + coff + t0))[l];
            ((float4*)(sm + TILE))[l]     = ((const float4*)(g_sy + coff + t0))[l];
            ((float4*)(sm + 2 * TILE))[l] = ((const float4*)(g_sz + coff + t0))[l];
            ((float4*)(sm + 3 * TILE))[l] = ((const float4*)(g_sw + coff + t0))[l];
        }
        __syncthreads();

        const float* base = sm + 4 * half;
#pragma unroll 4
        for (int j = 0; j < TILE; j += 8) {
            const ulonglong2 X = *(const ulonglong2*)(base + j);
            const ulonglong2 Y = *(const ulonglong2*)(base + j + TILE);
            const ulonglong2 Z = *(const ulonglong2*)(base + j + 2 * TILE);
            const ulonglong2 W = *(const ulonglong2*)(base + j + 3 * TILE);

            u64 t01 = ffma2(ax2, X.x, ffma2(ay2, Y.x, ffma2(az2, Z.x, W.x)));
            u64 t23 = ffma2(ax2, X.y, ffma2(ay2, Y.y, ffma2(az2, Z.y, W.y)));

            float f0 = lo32(t01), f1 = hi32(t01);
            float f2 = lo32(t23), f3 = hi32(t23);

            float m = fminf(fminf(f0, f1), fminf(f2, f3));
            if (m < h[0]) {
                TRYINS(h, f0); TRYINS(h, f1);
                TRYINS(h, f2); TRYINS(h, f3);
            }
        }

        // ---- update block threshold R^2 = max_q (h[0] + |q|^2)
        {
            float v = h[0] + q.w;
#pragma unroll
            for (int off = 16; off > 0; off >>= 1)
                v = fmaxf(v, __shfl_xor_sync(0xFFFFFFFFu, v, off));
            if (lane == 0) rpart[warp] = v;
        }
        __syncthreads();
        if (threadIdx.x == 0)
            R2s = fmaxf(fmaxf(rpart[0], rpart[1]), fmaxf(rpart[2], rpart[3]));
        __syncthreads();
    }

    // ---- merge the two halves' top-8 lists
    if (half) {
#pragma unroll
        for (int i = 0; i < KNN; ++i) m8[qt][i] = h[i];
    }
    __syncthreads();
    if (!half) {
#pragma unroll
        for (int i = 0; i < KNN; ++i)
            TRYINS(h, m8[qt][i]);
        float s = 0.0f;
#pragma unroll
        for (int i = 0; i < KNN; ++i)
            s += sqrtf(fmaxf(q.w + h[i], 0.0f));
        red[qt] = s;
    }
    __syncthreads();
#pragma unroll
    for (int off = QBLK / 2; off > 0; off >>= 1) {
        if (threadIdx.x < off) red[threadIdx.x] += red[threadIdx.x + off];
        __syncthreads();
    }
    if (threadIdx.x == 0)
        atomicAdd(out, red[0] * (1.0f / (KNN * BATCH * NPTS)));
}

extern "C" void kernel_launch(void* const* d_in, const int* in_sizes, int n_in,
                              void* d_out, int out_size) {
    const float* src  = (const float*)d_in[0];
    const float* tgt  = (const float*)d_in[1];
    const float* flow = (const float*)d_in[2];
    float* out = (float*)d_out;

    cudaMemsetAsync(out, 0, sizeof(float), 0);

    int npts = BATCH * NPTS;
    prep_kernel<<<(npts + 255) / 256, 256>>>(src, tgt, flow);
    sort_kernel<<<8, 1024>>>();
    tbox_kernel<<<2 * BATCH * NTILES, 256>>>();

    dim3 grid(NPTS / QBLK, BATCH, 2);
    chamfer_kernel<<<grid, THREADS>>>(out);
}

// round 13
// speedup vs baseline: 1.1805x; 1.1703x over previous
#include <cuda_runtime.h>

#define BATCH   4
#define NPTS    8192
#define KNN     8
#define TILE    512
#define NTILES  (NPTS / TILE)   // 16
#define QBLK    64              // queries per block
#define THREADS 128             // 2 threads per query
#define NBUCK   512             // morton buckets (9 bits)
#define BSHIFT  22              // key >> 22 = top 9 morton bits

typedef unsigned long long u64;

__device__ float4 g_pred4[BATCH * NPTS];
__device__ float4 g_targ4[BATCH * NPTS];
__device__ float4 g_pred4s[BATCH * NPTS];   // Morton-bucketed queries
__device__ float4 g_targ4s[BATCH * NPTS];
__device__ unsigned g_key[2][BATCH * NPTS]; // (morton18 << 13) | idx13
// Bucketed candidate SoA: index = (set*BATCH + b)*NPTS + i
__device__ float g_sx[2 * BATCH * NPTS];
__device__ float g_sy[2 * BATCH * NPTS];
__device__ float g_sz[2 * BATCH * NPTS];
__device__ float g_sw[2 * BATCH * NPTS];
// Tile AABBs: [(set*BATCH+b)*NTILES + t] * 6
__device__ float g_tbox[2 * BATCH * NTILES * 6];

__device__ __forceinline__ u64 pack2(float lo, float hi) {
    u64 r;
    asm("mov.b64 %0, {%1, %2};" : "=l"(r) : "f"(lo), "f"(hi));
    return r;
}
__device__ __forceinline__ float lo32(u64 v) { return __uint_as_float((unsigned)v); }
__device__ __forceinline__ float hi32(u64 v) { return __uint_as_float((unsigned)(v >> 32)); }
__device__ __forceinline__ u64 ffma2(u64 a, u64 b, u64 c) {
    u64 d;
    asm("fma.rn.f32x2 %0, %1, %2, %3;" : "=l"(d) : "l"(a), "l"(b), "l"(c));
    return d;
}

__device__ __forceinline__ unsigned morton18(float x, float y, float z) {
    int ax = (int)((x + 4.0f) * 8.0f); ax = ax < 0 ? 0 : (ax > 63 ? 63 : ax);
    int ay = (int)((y + 4.0f) * 8.0f); ay = ay < 0 ? 0 : (ay > 63 ? 63 : ay);
    int az = (int)((z + 4.0f) * 8.0f); az = az < 0 ? 0 : (az > 63 ? 63 : az);
    unsigned m = 0;
#pragma unroll
    for (int bit = 0; bit < 6; ++bit) {
        m |= ((unsigned)((ax >> bit) & 1)) << (3 * bit + 2);
        m |= ((unsigned)((ay >> bit) & 1)) << (3 * bit + 1);
        m |= ((unsigned)((az >> bit) & 1)) << (3 * bit + 0);
    }
    return m;
}

__global__ void prep_kernel(const float* __restrict__ src,
                            const float* __restrict__ tgt,
                            const float* __restrict__ flow) {
    int i = blockIdx.x * blockDim.x + threadIdx.x;
    if (i >= BATCH * NPTS) return;
    int li = i & (NPTS - 1);

    float px = src[3 * i + 0] + flow[3 * i + 0];
    float py = src[3 * i + 1] + flow[3 * i + 1];
    float pz = src[3 * i + 2] + flow[3 * i + 2];
    g_pred4[i] = make_float4(px, py, pz, px * px + py * py + pz * pz);
    g_key[0][i] = (morton18(px, py, pz) << 13) | (unsigned)li;

    float tx = tgt[3 * i + 0], ty = tgt[3 * i + 1], tz = tgt[3 * i + 2];
    g_targ4[i] = make_float4(tx, ty, tz, tx * tx + ty * ty + tz * tz);
    g_key[1][i] = (morton18(tx, ty, tz) << 13) | (unsigned)li;
}

// Morton-bucket counting sort: histogram -> scan -> scatter.
// grid = 8 blocks: blockIdx.x = set * BATCH + batch, 1024 threads.
__global__ void __launch_bounds__(1024)
csort_kernel() {
    __shared__ unsigned hist[NBUCK];
    __shared__ unsigned scn[NBUCK];
    __shared__ unsigned off[NBUCK];
    const int set = blockIdx.x >> 2;
    const int b   = blockIdx.x & 3;
    const int tid = threadIdx.x;
    const unsigned* key = g_key[set] + b * NPTS;

    for (int i = tid; i < NBUCK; i += 1024) hist[i] = 0;
    __syncthreads();
    for (int i = tid; i < NPTS; i += 1024)
        atomicAdd(&hist[key[i] >> BSHIFT], 1u);
    __syncthreads();

    // Hillis-Steele inclusive scan over NBUCK
    if (tid < NBUCK) scn[tid] = hist[tid];
    __syncthreads();
    for (int d = 1; d < NBUCK; d <<= 1) {
        unsigned v = 0;
        if (tid < NBUCK) {
            v = scn[tid];
            if (tid >= d) v += scn[tid - d];
        }
        __syncthreads();
        if (tid < NBUCK) scn[tid] = v;
        __syncthreads();
    }
    if (tid < NBUCK) off[tid] = scn[tid] - hist[tid];   // exclusive
    __syncthreads();

    const float4* src4 = (set == 0 ? g_pred4 : g_targ4) + b * NPTS;
    float4* dst4 = (set == 0 ? g_pred4s : g_targ4s) + b * NPTS;
    const int so = (set * BATCH + b) * NPTS;
    for (int i = tid; i < NPTS; i += 1024) {
        unsigned kv = key[i];
        unsigned pos = atomicAdd(&off[kv >> BSHIFT], 1u);
        float4 p = src4[kv & (NPTS - 1)];
        dst4[pos] = p;
        g_sx[so + pos] = p.x;
        g_sy[so + pos] = p.y;
        g_sz[so + pos] = p.z;
        g_sw[so + pos] = p.w;
    }
}

// Per-tile AABB. blockIdx.x = (set*BATCH+b)*NTILES + t, 256 threads.
__global__ void __launch_bounds__(256)
tbox_kernel() {
    __shared__ float rlo[3][256], rhi[3][256];
    const int id  = blockIdx.x;
    const int t   = id % NTILES;
    const int sb  = id / NTILES;
    const int bse = sb * NPTS + t * TILE;
    const int tid = threadIdx.x;

    float lx = 1e30f, ly = 1e30f, lz = 1e30f;
    float hx = -1e30f, hy = -1e30f, hz = -1e30f;
    for (int i = tid; i < TILE; i += 256) {
        float x = g_sx[bse + i], y = g_sy[bse + i], z = g_sz[bse + i];
        lx = fminf(lx, x); ly = fminf(ly, y); lz = fminf(lz, z);
        hx = fmaxf(hx, x); hy = fmaxf(hy, y); hz = fmaxf(hz, z);
    }
    rlo[0][tid] = lx; rlo[1][tid] = ly; rlo[2][tid] = lz;
    rhi[0][tid] = hx; rhi[1][tid] = hy; rhi[2][tid] = hz;
    __syncthreads();
    for (int off = 128; off > 0; off >>= 1) {
        if (tid < off) {
#pragma unroll
            for (int d = 0; d < 3; ++d) {
                rlo[d][tid] = fminf(rlo[d][tid], rlo[d][tid + off]);
                rhi[d][tid] = fmaxf(rhi[d][tid], rhi[d][tid + off]);
            }
        }
        __syncthreads();
    }
    if (tid == 0) {
        g_tbox[id * 6 + 0] = rlo[0][0];
        g_tbox[id * 6 + 1] = rlo[1][0];
        g_tbox[id * 6 + 2] = rlo[2][0];
        g_tbox[id * 6 + 3] = rhi[0][0];
        g_tbox[id * 6 + 4] = rhi[1][0];
        g_tbox[id * 6 + 5] = rhi[2][0];
    }
}

// Branchless sorted-descending insert (caller guarantees val < h[0])
#define INSERT8(h, val)                          \
    do {                                         \
        float _v = (val);                        \
        _Pragma("unroll")                        \
        for (int _i = 0; _i < KNN - 1; ++_i) {   \
            float _nx = h[_i + 1];               \
            h[_i] = fmaxf(_v, _nx);              \
            _v = fminf(_v, _nx);                 \
        }                                        \
        h[KNN - 1] = _v;                         \
    } while (0)

#define TRYINS(h, val) do { if ((val) < h[0]) INSERT8(h, (val)); } while (0)

__global__ void __launch_bounds__(THREADS, 8)
chamfer_kernel(float* __restrict__ out) {
    __shared__ __align__(16) float sm[4 * TILE];
    __shared__ float m8[QBLK][KNN];
    __shared__ float red[QBLK];
    __shared__ float qpart[4][6];
    __shared__ float rpart[4];
    __shared__ float mind2s[NTILES];
    __shared__ int   order_s[NTILES];
    __shared__ float R2s;

    const int b   = blockIdx.y;
    const int dir = blockIdx.z;
    const float4* q4 = (dir == 0 ? g_pred4s : g_targ4s) + b * NPTS;
    const int sb   = (dir == 0 ? 1 : 0) * BATCH + b;   // candidate set-batch
    const int coff = sb * NPTS;

    const int qt   = threadIdx.x & (QBLK - 1);
    const int half = threadIdx.x >> 6;       // warp-uniform
    const int warp = threadIdx.x >> 5;
    const int lane = threadIdx.x & 31;
    const int qi   = blockIdx.x * QBLK + qt;
    const float4 q = q4[qi];
    const u64 ax2 = pack2(-2.0f * q.x, -2.0f * q.x);
    const u64 ay2 = pack2(-2.0f * q.y, -2.0f * q.y);
    const u64 az2 = pack2(-2.0f * q.z, -2.0f * q.z);

    // ---- query-block AABB
    {
        float lx = q.x, ly = q.y, lz = q.z;
        float hx = q.x, hy = q.y, hz = q.z;
#pragma unroll
        for (int off = 16; off > 0; off >>= 1) {
            lx = fminf(lx, __shfl_xor_sync(0xFFFFFFFFu, lx, off));
            ly = fminf(ly, __shfl_xor_sync(0xFFFFFFFFu, ly, off));
            lz = fminf(lz, __shfl_xor_sync(0xFFFFFFFFu, lz, off));
            hx = fmaxf(hx, __shfl_xor_sync(0xFFFFFFFFu, hx, off));
            hy = fmaxf(hy, __shfl_xor_sync(0xFFFFFFFFu, hy, off));
            hz = fmaxf(hz, __shfl_xor_sync(0xFFFFFFFFu, hz, off));
        }
        if (lane == 0) {
            qpart[warp][0] = lx; qpart[warp][1] = ly; qpart[warp][2] = lz;
            qpart[warp][3] = hx; qpart[warp][4] = hy; qpart[warp][5] = hz;
        }
    }
    __syncthreads();

    // ---- thread 0: per-tile mindist^2, sort tiles ascending
    if (threadIdx.x == 0) {
        float qb[6];
#pragma unroll
        for (int d = 0; d < 3; ++d) {
            qb[d]     = fminf(fminf(qpart[0][d], qpart[1][d]),
                              fminf(qpart[2][d], qpart[3][d]));
            qb[d + 3] = fmaxf(fmaxf(qpart[0][d + 3], qpart[1][d + 3]),
                              fmaxf(qpart[2][d + 3], qpart[3][d + 3]));
        }
        float md[NTILES];
        int   od[NTILES];
#pragma unroll
        for (int t = 0; t < NTILES; ++t) {
            const float* tb = g_tbox + (sb * NTILES + t) * 6;
            float s = 0.0f;
#pragma unroll
            for (int d = 0; d < 3; ++d) {
                float g = fmaxf(fmaxf(tb[d] - qb[d + 3], qb[d] - tb[d + 3]), 0.0f);
                s += g * g;
            }
            md[t] = s;
            od[t] = t;
        }
        for (int i = 1; i < NTILES; ++i) {
            float mv = md[i]; int ov = od[i];
            int j = i;
            while (j > 0 && md[j - 1] > mv) { md[j] = md[j - 1]; od[j] = od[j - 1]; --j; }
            md[j] = mv; od[j] = ov;
        }
#pragma unroll
        for (int t = 0; t < NTILES; ++t) { mind2s[t] = md[t]; order_s[t] = od[t]; }
        R2s = 1e30f;
    }

    float h[KNN];
#pragma unroll
    for (int i = 0; i < KNN; ++i) h[i] = 1.0e30f;

    __syncthreads();

    for (int k = 0; k < NTILES; ++k) {
        if (k > 0 && mind2s[k] > R2s) break;   // block-uniform, exact cull
        const int t0 = order_s[k] * TILE;
        __syncthreads();
#pragma unroll
        for (int l = threadIdx.x; l < TILE / 4; l += THREADS) {
            ((float4*)sm)[l]              = ((const float4*)(g_sx + coff + t0))[l];
            ((float4*)(sm + TILE))[l]     = ((const float4*)(g_sy + coff + t0))[l];
            ((float4*)(sm + 2 * TILE))[l] = ((const float4*)(g_sz + coff + t0))[l];
            ((float4*)(sm + 3 * TILE))[l] = ((const float4*)(g_sw + coff + t0))[l];
        }
        __syncthreads();

        const float* base = sm + 4 * half;
#pragma unroll 4
        for (int j = 0; j < TILE; j += 8) {
            const ulonglong2 X = *(const ulonglong2*)(base + j);
            const ulonglong2 Y = *(const ulonglong2*)(base + j + TILE);
            const ulonglong2 Z = *(const ulonglong2*)(base + j + 2 * TILE);
            const ulonglong2 W = *(const ulonglong2*)(base + j + 3 * TILE);

            u64 t01 = ffma2(ax2, X.x, ffma2(ay2, Y.x, ffma2(az2, Z.x, W.x)));
            u64 t23 = ffma2(ax2, X.y, ffma2(ay2, Y.y, ffma2(az2, Z.y, W.y)));

            float f0 = lo32(t01), f1 = hi32(t01);
            float f2 = lo32(t23), f3 = hi32(t23);

            float m = fminf(fminf(f0, f1), fminf(f2, f3));
            if (m < h[0]) {
                TRYINS(h, f0); TRYINS(h, f1);
                TRYINS(h, f2); TRYINS(h, f3);
            }
        }

        // ---- update block threshold R^2 = max_q (h[0] + |q|^2)
        {
            float v = h[0] + q.w;
#pragma unroll
            for (int off = 16; off > 0; off >>= 1)
                v = fmaxf(v, __shfl_xor_sync(0xFFFFFFFFu, v, off));
            if (lane == 0) rpart[warp] = v;
        }
        __syncthreads();
        if (threadIdx.x == 0)
            R2s = fmaxf(fmaxf(rpart[0], rpart[1]), fmaxf(rpart[2], rpart[3]));
        __syncthreads();
    }

    // ---- merge the two halves' top-8 lists
    if (half) {
#pragma unroll
        for (int i = 0; i < KNN; ++i) m8[qt][i] = h[i];
    }
    __syncthreads();
    if (!half) {
#pragma unroll
        for (int i = 0; i < KNN; ++i)
            TRYINS(h, m8[qt][i]);
        float s = 0.0f;
#pragma unroll
        for (int i = 0; i < KNN; ++i)
            s += sqrtf(fmaxf(q.w + h[i], 0.0f));
        red[qt] = s;
    }
    __syncthreads();
#pragma unroll
    for (int off = QBLK / 2; off > 0; off >>= 1) {
        if (threadIdx.x < off) red[threadIdx.x] += red[threadIdx.x + off];
        __syncthreads();
    }
    if (threadIdx.x == 0)
        atomicAdd(out, red[0] * (1.0f / (KNN * BATCH * NPTS)));
}

extern "C" void kernel_launch(void* const* d_in, const int* in_sizes, int n_in,
                              void* d_out, int out_size) {
    const float* src  = (const float*)d_in[0];
    const float* tgt  = (const float*)d_in[1];
    const float* flow = (const float*)d_in[2];
    float* out = (float*)d_out;

    cudaMemsetAsync(out, 0, sizeof(float), 0);

    int npts = BATCH * NPTS;
    prep_kernel<<<(npts + 255) / 256, 256>>>(src, tgt, flow);
    csort_kernel<<<8, 1024>>>();
    tbox_kernel<<<2 * BATCH * NTILES, 256>>>();

    dim3 grid(NPTS / QBLK, BATCH, 2);
    chamfer_kernel<<<grid, THREADS>>>(out);
}